// round 1
// baseline (speedup 1.0000x reference)
#include <cuda_runtime.h>

#define NN 8192
#define FIN 512
#define FOUT 64
#define BM 64
#define BK 128

// Scratch (no allocations allowed)
__device__ float g_h[NN * FOUT];
__device__ float g_ssrc[NN];
__device__ float g_sdst[NN];
__device__ float g_G[NN];     // exp(0.8 * s_src)
__device__ float g_F[NN];     // exp(s_dst)
__device__ float g_F02[NN];   // exp(0.2 * s_dst)

// ---------- packed f32x2 helpers ----------
__device__ __forceinline__ unsigned long long dup2(float p) {
    unsigned long long r;
    unsigned int u = __float_as_uint(p);
    asm("mov.b64 %0, {%1, %1};" : "=l"(r) : "r"(u));
    return r;
}
__device__ __forceinline__ void fma2(unsigned long long& d, unsigned long long a, unsigned long long b) {
    asm("fma.rn.f32x2 %0, %1, %2, %0;" : "+l"(d) : "l"(a), "l"(b));
}
__device__ __forceinline__ void unpack2(unsigned long long v, float& x, float& y) {
    unsigned int a, b;
    asm("mov.b64 {%0, %1}, %2;" : "=r"(a), "=r"(b) : "l"(v));
    x = __uint_as_float(a);
    y = __uint_as_float(b);
}

// ---------- Kernel A: h = X @ W  (8192x512 @ 512x64) ----------
__global__ __launch_bounds__(256) void k_gemm_h(const float* __restrict__ X,
                                                const float* __restrict__ W,
                                                float* __restrict__ H) {
    __shared__ float sA[32][65];  // [k][m] transposed
    __shared__ float sB[32][68];  // [k][n]
    int t = threadIdx.x;
    int m0 = blockIdx.x * 64;
    int tr = t >> 4;   // 0..15
    int tc = t & 15;   // 0..15
    float acc[4][4];
#pragma unroll
    for (int i = 0; i < 4; i++)
#pragma unroll
        for (int j = 0; j < 4; j++) acc[i][j] = 0.f;

    for (int k0 = 0; k0 < FIN; k0 += 32) {
        __syncthreads();
#pragma unroll
        for (int u = 0; u < 8; u++) {
            int g = u * 256 + t;         // 0..2047
            int m = g >> 5, k = g & 31;  // coalesced along k
            sA[k][m] = X[(m0 + m) * FIN + k0 + k];
        }
#pragma unroll
        for (int u = 0; u < 8; u++) {
            int g = u * 256 + t;
            int k = g >> 6, n = g & 63;  // coalesced along n
            sB[k][n] = W[(k0 + k) * FOUT + n];
        }
        __syncthreads();
#pragma unroll
        for (int k = 0; k < 32; k++) {
            float a[4], b[4];
#pragma unroll
            for (int i = 0; i < 4; i++) a[i] = sA[k][tr + 16 * i];
#pragma unroll
            for (int j = 0; j < 4; j++) b[j] = sB[k][tc + 16 * j];
#pragma unroll
            for (int i = 0; i < 4; i++)
#pragma unroll
                for (int j = 0; j < 4; j++) acc[i][j] += a[i] * b[j];
        }
    }
#pragma unroll
    for (int i = 0; i < 4; i++)
#pragma unroll
        for (int j = 0; j < 4; j++)
            H[(m0 + tr + 16 * i) * FOUT + tc + 16 * j] = acc[i][j];
}

// ---------- Kernel A2: scores + exp factors ----------
__global__ __launch_bounds__(256) void k_scores(const float* __restrict__ H,
                                                const float* __restrict__ a) {
    int i = blockIdx.x * blockDim.x + threadIdx.x;
    const float4* hr = (const float4*)(H + i * FOUT);
    const float4* av = (const float4*)a;
    float ss = 0.f, sd = 0.f;
#pragma unroll
    for (int f = 0; f < 16; f++) {
        float4 h = hr[f];
        float4 as = av[f];
        float4 ad = av[16 + f];
        ss += h.x * as.x + h.y * as.y + h.z * as.z + h.w * as.w;
        sd += h.x * ad.x + h.y * ad.y + h.z * ad.z + h.w * ad.w;
    }
    g_ssrc[i] = ss;
    g_sdst[i] = sd;
    g_G[i] = expf(0.8f * ss);
    g_F[i] = expf(sd);
    g_F02[i] = expf(0.2f * sd);
}

// ---------- Kernel B: fused masked softmax + P@h + ELU ----------
// smem layout (floats):
//   sP   [BM][BK+4]      = 64*132
//   sH   [BK][FOUT+4]    = 128*68
//   sSum [BM]
//   sF, sF02, sSd [BK] each
#define SP_STRIDE (BK + 4)
#define SH_STRIDE (FOUT + 4)
#define SMEM_FLOATS (BM * SP_STRIDE + BK * SH_STRIDE + BM + 3 * BK)

__global__ __launch_bounds__(256) void k_attn(const int* __restrict__ adj,
                                              float* __restrict__ out) {
    extern __shared__ float smem[];
    float* sP = smem;                                // [BM][SP_STRIDE]
    float* sH = sP + BM * SP_STRIDE;                 // [BK][SH_STRIDE]
    float* sSum = sH + BK * SH_STRIDE;               // [BM]
    float* sF = sSum + BM;                           // [BK]
    float* sF02 = sF + BK;
    float* sSd = sF02 + BK;

    int t = threadIdx.x;
    int i0 = blockIdx.x * BM;

    // P-build mapping: thread covers row pr, cols {pcl + 16u + s}
    int pr = t >> 2;            // 0..63
    int pcl = (t & 3) * 4;      // 0,4,8,12
    float si = g_ssrc[i0 + pr];
    float Gi = g_G[i0 + pr];
    if (t < BM) sSum[t] = 0.f;

    // GEMM mapping: 8 warps as 2 rowgroups x 4 colgroups; thread tile 4x4
    int w = t >> 5, l = t & 31;
    int gr0 = (w >> 2) * 32 + (l >> 2);        // + 8*i for i<4
    int gc0 = (w & 3) * 16 + (l & 3) * 4;      // 4 consecutive cols
    unsigned long long acc[4][2];
#pragma unroll
    for (int i = 0; i < 4; i++) { acc[i][0] = 0ULL; acc[i][1] = 0ULL; }

    const int* adjrow = adj + (i0 + pr) * NN;

    for (int j0 = 0; j0 < NN; j0 += BK) {
        __syncthreads();
        // load H tile (128x64) coalesced float4
        const float4* hsrc = (const float4*)(g_h + j0 * FOUT);
#pragma unroll
        for (int u = 0; u < 8; u++) {
            int g = u * 256 + t;          // float4 index 0..2047
            int k = g >> 4, c4 = g & 15;
            float4 v = hsrc[g];
            *(float4*)&sH[k * SH_STRIDE + c4 * 4] = v;
        }
        if (t < BK) {
            sF[t] = g_F[j0 + t];
            sF02[t] = g_F02[j0 + t];
            sSd[t] = g_sdst[j0 + t];
        }
        __syncthreads();

        // build P tile + local row sums
        float lsum = 0.f;
#pragma unroll
        for (int u = 0; u < 8; u++) {
            int cb = pcl + 16 * u;
            int4 av = *(const int4*)(adjrow + j0 + cb);
            float4 p;
            {
                float td = sSd[cb + 0];
                p.x = (av.x > 0) ? ((si + td >= 0.f) ? Gi * sF[cb + 0] : sF02[cb + 0]) : 0.f;
            }
            {
                float td = sSd[cb + 1];
                p.y = (av.y > 0) ? ((si + td >= 0.f) ? Gi * sF[cb + 1] : sF02[cb + 1]) : 0.f;
            }
            {
                float td = sSd[cb + 2];
                p.z = (av.z > 0) ? ((si + td >= 0.f) ? Gi * sF[cb + 2] : sF02[cb + 2]) : 0.f;
            }
            {
                float td = sSd[cb + 3];
                p.w = (av.w > 0) ? ((si + td >= 0.f) ? Gi * sF[cb + 3] : sF02[cb + 3]) : 0.f;
            }
            lsum += (p.x + p.y) + (p.z + p.w);
            *(float4*)&sP[pr * SP_STRIDE + cb] = p;
        }
        atomicAdd(&sSum[pr], lsum);
        __syncthreads();

        // GEMM: acc[64x64] += P[64xBK] @ H[BKx64], f32x2 packed FMA
#pragma unroll 2
        for (int k = 0; k < BK; k += 4) {
            float4 pf[4];
#pragma unroll
            for (int i = 0; i < 4; i++)
                pf[i] = *(const float4*)&sP[(gr0 + 8 * i) * SP_STRIDE + k];
#pragma unroll
            for (int kk = 0; kk < 4; kk++) {
                ulonglong2 hv = *(const ulonglong2*)&sH[(k + kk) * SH_STRIDE + gc0];
#pragma unroll
                for (int i = 0; i < 4; i++) {
                    float ps = (kk == 0) ? pf[i].x : (kk == 1) ? pf[i].y : (kk == 2) ? pf[i].z : pf[i].w;
                    unsigned long long pd = dup2(ps);
                    fma2(acc[i][0], pd, hv.x);
                    fma2(acc[i][1], pd, hv.y);
                }
            }
        }
    }

    // epilogue: normalize + ELU (all atomicAdds precede the last __syncthreads)
#pragma unroll
    for (int i = 0; i < 4; i++) {
        int r = gr0 + 8 * i;
        float inv = 1.0f / sSum[r];
        float4 o;
        unpack2(acc[i][0], o.x, o.y);
        unpack2(acc[i][1], o.z, o.w);
        o.x *= inv; o.y *= inv; o.z *= inv; o.w *= inv;
        o.x = (o.x > 0.f) ? o.x : expm1f(o.x);
        o.y = (o.y > 0.f) ? o.y : expm1f(o.y);
        o.z = (o.z > 0.f) ? o.z : expm1f(o.z);
        o.w = (o.w > 0.f) ? o.w : expm1f(o.w);
        *(float4*)&out[(i0 + r) * FOUT + gc0] = o;
    }
}

extern "C" void kernel_launch(void* const* d_in, const int* in_sizes, int n_in,
                              void* d_out, int out_size) {
    const float* X = (const float*)d_in[0];   // 8192x512
    const int* adj = (const int*)d_in[1];     // 8192x8192
    const float* W = (const float*)d_in[2];   // 512x64
    const float* a = (const float*)d_in[3];   // 128x1
    float* out = (float*)d_out;               // 8192x64

    float* H;
    cudaGetSymbolAddress((void**)&H, g_h);

    static int smem_set = 0;
    int smem_bytes = SMEM_FLOATS * (int)sizeof(float);
    if (!smem_set) {
        cudaFuncSetAttribute(k_attn, cudaFuncAttributeMaxDynamicSharedMemorySize, smem_bytes);
        smem_set = 1;
    }

    k_gemm_h<<<NN / 64, 256>>>(X, W, H);
    k_scores<<<NN / 256, 256>>>(H, a);
    k_attn<<<NN / BM, 256, smem_bytes>>>(adj, out);
}

// round 6
// speedup vs baseline: 1.8000x; 1.8000x over previous
#include <cuda_runtime.h>
#include <cuda_bf16.h>
#include <cstdint>

#define NN 8192
#define FIN 512
#define FOUT 64

// ---------------- scratch globals (no allocations allowed) ----------------
__device__ float g_h[NN * FOUT];
__device__ float g_ssrc[NN];
__device__ float g_G[NN];                    // exp(0.8 * s_src)
__device__ float4 g_colf[NN];                // {F=exp(sd), F02=exp(0.2 sd), sd, 0}
__device__ __nv_bfloat16 g_HThi[FOUT * NN];  // H^T high bf16, [f][i]
__device__ __nv_bfloat16 g_HTlo[FOUT * NN];  // H^T residual bf16
__device__ float g_part[2 * NN * FOUT];      // partial numerators per j-half
__device__ float g_psum[2 * NN];             // partial row sums per j-half

// ---------------- Kernel A: h = X @ W ----------------
__global__ __launch_bounds__(256) void k_gemm_h(const float* __restrict__ X,
                                                const float* __restrict__ W,
                                                float* __restrict__ H) {
    __shared__ float sA[32][65];
    __shared__ float sB[32][68];
    int t = threadIdx.x;
    int m0 = blockIdx.x * 64;
    int tr = t >> 4, tc = t & 15;
    float acc[4][4];
#pragma unroll
    for (int i = 0; i < 4; i++)
#pragma unroll
        for (int j = 0; j < 4; j++) acc[i][j] = 0.f;

    float rA[8], rB[8];
#pragma unroll
    for (int u = 0; u < 8; u++) {
        int g = u * 256 + t;
        int m = g >> 5, k = g & 31;
        rA[u] = X[(m0 + m) * FIN + k];
    }
#pragma unroll
    for (int u = 0; u < 8; u++) {
        int g = u * 256 + t;
        int k = g >> 6, n = g & 63;
        rB[u] = W[k * FOUT + n];
    }

    for (int kc = 0; kc < 16; kc++) {
        __syncthreads();
#pragma unroll
        for (int u = 0; u < 8; u++) {
            int g = u * 256 + t;
            int m = g >> 5, k = g & 31;
            sA[k][m] = rA[u];
        }
#pragma unroll
        for (int u = 0; u < 8; u++) {
            int g = u * 256 + t;
            int k = g >> 6, n = g & 63;
            sB[k][n] = rB[u];
        }
        __syncthreads();
        if (kc + 1 < 16) {
            int k0 = (kc + 1) * 32;
#pragma unroll
            for (int u = 0; u < 8; u++) {
                int g = u * 256 + t;
                int m = g >> 5, k = g & 31;
                rA[u] = X[(m0 + m) * FIN + k0 + k];
            }
#pragma unroll
            for (int u = 0; u < 8; u++) {
                int g = u * 256 + t;
                int k = g >> 6, n = g & 63;
                rB[u] = W[(k0 + k) * FOUT + n];
            }
        }
#pragma unroll
        for (int k = 0; k < 32; k++) {
            float a[4], b[4];
#pragma unroll
            for (int i = 0; i < 4; i++) a[i] = sA[k][tr + 16 * i];
#pragma unroll
            for (int j = 0; j < 4; j++) b[j] = sB[k][tc + 16 * j];
#pragma unroll
            for (int i = 0; i < 4; i++)
#pragma unroll
                for (int j = 0; j < 4; j++) acc[i][j] += a[i] * b[j];
        }
    }
#pragma unroll
    for (int i = 0; i < 4; i++)
#pragma unroll
        for (int j = 0; j < 4; j++)
            H[(m0 + tr + 16 * i) * FOUT + tc + 16 * j] = acc[i][j];
}

// ---------------- Kernel A2: scores + exp factors ----------------
__global__ __launch_bounds__(256) void k_scores(const float* __restrict__ H,
                                                const float* __restrict__ a) {
    int i = blockIdx.x * blockDim.x + threadIdx.x;
    const float4* hr = (const float4*)(H + i * FOUT);
    const float4* av = (const float4*)a;
    float ss = 0.f, sd = 0.f;
#pragma unroll
    for (int f = 0; f < 16; f++) {
        float4 h = hr[f];
        float4 as = av[f];
        float4 ad = av[16 + f];
        ss += h.x * as.x + h.y * as.y + h.z * as.z + h.w * as.w;
        sd += h.x * ad.x + h.y * ad.y + h.z * ad.z + h.w * ad.w;
    }
    g_ssrc[i] = ss;
    g_G[i] = expf(0.8f * ss);
    g_colf[i] = make_float4(expf(sd), expf(0.2f * sd), sd, 0.f);
}

// ---------------- Kernel A3: transpose H -> HT hi/lo bf16 ----------------
__global__ __launch_bounds__(256) void k_transpose() {
    __shared__ float tile[64][65];
    int t = threadIdx.x;
    int i0 = blockIdx.x * 64;
#pragma unroll
    for (int u = 0; u < 16; u++) {
        int idx = u * 256 + t;
        int r = idx >> 6, c = idx & 63;
        tile[r][c] = g_h[(i0 + r) * FOUT + c];
    }
    __syncthreads();
#pragma unroll
    for (int u = 0; u < 16; u++) {
        int idx = u * 256 + t;
        int f = idx >> 6, i = idx & 63;
        float v = tile[i][f];
        __nv_bfloat16 hb = __float2bfloat16(v);
        float hv = __bfloat162float(hb);
        __nv_bfloat16 lb = __float2bfloat16(v - hv);
        g_HThi[f * NN + i0 + i] = hb;
        g_HTlo[f * NN + i0 + i] = lb;
    }
}

// ---------------- Kernel B: HMMA attention ----------------
// smem (u32 units): stride per row = 68 u32 (= 136 bf16, 272 B; conflict-free)
#define SPS 68
#define SP_HI_U32 0                    // P hi: 128 rows x 68  = 8704 u32
#define SP_LO_U32 8704                 // P lo: 8704
#define SB_HI_U32 17408                // B hi: 64 rows x 68 = 4352
#define SB_LO_U32 21760                // B lo: 4352
#define SMEM_U32 26112                 // total = 104448 B

__device__ __forceinline__ void mma_bf16(float* c, const uint32_t* a, uint32_t b0, uint32_t b1) {
    asm volatile(
        "mma.sync.aligned.m16n8k16.row.col.f32.bf16.bf16.f32 "
        "{%0,%1,%2,%3}, {%4,%5,%6,%7}, {%8,%9}, {%0,%1,%2,%3};"
        : "+f"(c[0]), "+f"(c[1]), "+f"(c[2]), "+f"(c[3])
        : "r"(a[0]), "r"(a[1]), "r"(a[2]), "r"(a[3]), "r"(b0), "r"(b1));
}

__global__ __launch_bounds__(256, 1) void k_attn(const int* __restrict__ adj) {
    extern __shared__ uint32_t sm[];
    uint32_t* sPhi = sm + SP_HI_U32;
    uint32_t* sPlo = sm + SP_LO_U32;
    uint32_t* sBhi = sm + SB_HI_U32;
    uint32_t* sBlo = sm + SB_LO_U32;

    int t = threadIdx.x;
    int w = t >> 5;
    int lane = t & 31;
    int g = lane >> 2, tg = lane & 3;
    int rb = blockIdx.x >> 1;
    int jh = blockIdx.x & 1;
    int i0 = rb * 128;
    int jbase = jh * 4096;

    // P-build mapping
    int row = t >> 1;
    int half = t & 1;
    float si = g_ssrc[i0 + row];
    float Gi = g_G[i0 + row];
    float nsi = -si;
    float rsum = 0.f;
    const int* adjrow = adj + (size_t)(i0 + row) * NN + jbase + half * 64;
    uint64_t* pDhi = (uint64_t*)sPhi + (size_t)row * (SPS / 2) + half * 16;
    uint64_t* pDlo = (uint64_t*)sPlo + (size_t)row * (SPS / 2) + half * 16;

    // MMA mapping: 8 warps = 4 row-groups x 2 col-groups; warp tile 32x32
    int wr = w >> 1, wc = w & 1;
    float acc[2][4][4];
#pragma unroll
    for (int mi = 0; mi < 2; mi++)
#pragma unroll
        for (int ni = 0; ni < 4; ni++)
#pragma unroll
            for (int q = 0; q < 4; q++) acc[mi][ni][q] = 0.f;

    for (int tt = 0; tt < 32; tt++) {
        int jc = jbase + tt * 128;
        __syncthreads();

        // --- stage B tiles: H^T hi/lo [64 n][128 k] bf16, coalesced u32 ---
#pragma unroll
        for (int u = 0; u < 16; u++) {
            int idx = u * 256 + t;
            int f = idx >> 6, c2 = idx & 63;
            sBhi[f * SPS + c2] = ((const uint32_t*)(g_HThi + (size_t)f * NN + jc))[c2];
            sBlo[f * SPS + c2] = ((const uint32_t*)(g_HTlo + (size_t)f * NN + jc))[c2];
        }

        // --- build P tile: fp32 select -> bf16 hi/lo ---
        {
            const int4* a4 = (const int4*)(adjrow + tt * 128);
            const float4* colf = g_colf + jc + half * 64;
#pragma unroll 4
            for (int u = 0; u < 16; u++) {
                int4 av = a4[u];
                int l = u * 4;
                float4 c0 = colf[l + 0], c1 = colf[l + 1], c2v = colf[l + 2], c3 = colf[l + 3];
                float p0 = (av.x > 0) ? ((c0.z >= nsi) ? Gi * c0.x : c0.y) : 0.f;
                float p1 = (av.y > 0) ? ((c1.z >= nsi) ? Gi * c1.x : c1.y) : 0.f;
                float p2 = (av.z > 0) ? ((c2v.z >= nsi) ? Gi * c2v.x : c2v.y) : 0.f;
                float p3 = (av.w > 0) ? ((c3.z >= nsi) ? Gi * c3.x : c3.y) : 0.f;
                rsum += (p0 + p1) + (p2 + p3);
                uint32_t h01, h23, l01, l23;
                asm("cvt.rn.bf16x2.f32 %0, %1, %2;" : "=r"(h01) : "f"(p1), "f"(p0));
                asm("cvt.rn.bf16x2.f32 %0, %1, %2;" : "=r"(h23) : "f"(p3), "f"(p2));
                float q0 = p0 - __uint_as_float(h01 << 16);
                float q1 = p1 - __uint_as_float(h01 & 0xffff0000u);
                float q2 = p2 - __uint_as_float(h23 << 16);
                float q3 = p3 - __uint_as_float(h23 & 0xffff0000u);
                asm("cvt.rn.bf16x2.f32 %0, %1, %2;" : "=r"(l01) : "f"(q1), "f"(q0));
                asm("cvt.rn.bf16x2.f32 %0, %1, %2;" : "=r"(l23) : "f"(q3), "f"(q2));
                pDhi[u] = (uint64_t)h01 | ((uint64_t)h23 << 32);
                pDlo[u] = (uint64_t)l01 | ((uint64_t)l23 << 32);
            }
        }
        __syncthreads();

        // --- HMMA: acc += P[128x128] @ H^T[64x128]^T (3-pass hi/lo) ---
#pragma unroll
        for (int kk = 0; kk < 8; kk++) {
            int kb = kk * 8 + tg;
            uint32_t ah[2][4], al[2][4];
#pragma unroll
            for (int mi = 0; mi < 2; mi++) {
                int r0 = wr * 32 + mi * 16 + g;
                ah[mi][0] = sPhi[r0 * SPS + kb];
                ah[mi][1] = sPhi[(r0 + 8) * SPS + kb];
                ah[mi][2] = sPhi[r0 * SPS + kb + 4];
                ah[mi][3] = sPhi[(r0 + 8) * SPS + kb + 4];
                al[mi][0] = sPlo[r0 * SPS + kb];
                al[mi][1] = sPlo[(r0 + 8) * SPS + kb];
                al[mi][2] = sPlo[r0 * SPS + kb + 4];
                al[mi][3] = sPlo[(r0 + 8) * SPS + kb + 4];
            }
#pragma unroll
            for (int ni = 0; ni < 4; ni++) {
                int n0 = wc * 32 + ni * 8 + g;
                uint32_t bh0 = sBhi[n0 * SPS + kb];
                uint32_t bh1 = sBhi[n0 * SPS + kb + 4];
                uint32_t bl0 = sBlo[n0 * SPS + kb];
                uint32_t bl1 = sBlo[n0 * SPS + kb + 4];
#pragma unroll
                for (int mi = 0; mi < 2; mi++) {
                    mma_bf16(acc[mi][ni], ah[mi], bh0, bh1);
                    mma_bf16(acc[mi][ni], ah[mi], bl0, bl1);
                    mma_bf16(acc[mi][ni], al[mi], bh0, bh1);
                }
            }
        }
    }

    // row sums (combine the two halves of each row)
    {
        float o = __shfl_xor_sync(0xffffffffu, rsum, 1);
        if (half == 0) g_psum[(size_t)jh * NN + i0 + row] = rsum + o;
    }

    // store partial numerators
#pragma unroll
    for (int mi = 0; mi < 2; mi++) {
        int r0 = i0 + wr * 32 + mi * 16 + g;
#pragma unroll
        for (int ni = 0; ni < 4; ni++) {
            int c = wc * 32 + ni * 8 + tg * 2;
            float* base0 = g_part + ((size_t)jh * NN + r0) * FOUT + c;
            float* base1 = g_part + ((size_t)jh * NN + r0 + 8) * FOUT + c;
            *(float2*)base0 = make_float2(acc[mi][ni][0], acc[mi][ni][1]);
            *(float2*)base1 = make_float2(acc[mi][ni][2], acc[mi][ni][3]);
        }
    }
}

// ---------------- Kernel C: combine halves + normalize + ELU ----------------
__global__ __launch_bounds__(256) void k_combine(float* __restrict__ out) {
    int v = blockIdx.x * blockDim.x + threadIdx.x;  // float4 index
    int row = v >> 4;
    float s = g_psum[row] + g_psum[NN + row];
    float inv = 1.0f / s;
    float4 a0 = ((const float4*)g_part)[v];
    float4 a1 = ((const float4*)(g_part + (size_t)NN * FOUT))[v];
    float4 o;
    o.x = (a0.x + a1.x) * inv;
    o.y = (a0.y + a1.y) * inv;
    o.z = (a0.z + a1.z) * inv;
    o.w = (a0.w + a1.w) * inv;
    o.x = (o.x > 0.f) ? o.x : expm1f(o.x);
    o.y = (o.y > 0.f) ? o.y : expm1f(o.y);
    o.z = (o.z > 0.f) ? o.z : expm1f(o.z);
    o.w = (o.w > 0.f) ? o.w : expm1f(o.w);
    ((float4*)out)[v] = o;
}

extern "C" void kernel_launch(void* const* d_in, const int* in_sizes, int n_in,
                              void* d_out, int out_size) {
    const float* X = (const float*)d_in[0];   // 8192x512
    const int* adj = (const int*)d_in[1];     // 8192x8192
    const float* W = (const float*)d_in[2];   // 512x64
    const float* a = (const float*)d_in[3];   // 128x1
    float* out = (float*)d_out;               // 8192x64

    float* H;
    cudaGetSymbolAddress((void**)&H, g_h);

    static int inited = 0;
    if (!inited) {
        cudaFuncSetAttribute(k_attn, cudaFuncAttributeMaxDynamicSharedMemorySize,
                             SMEM_U32 * 4);
        inited = 1;
    }

    k_gemm_h<<<NN / 64, 256>>>(X, W, H);
    k_scores<<<NN / 256, 256>>>(H, a);
    k_transpose<<<NN / 64, 256>>>();
    k_attn<<<128, 256, SMEM_U32 * 4>>>(adj);
    k_combine<<<(NN * FOUT / 4) / 256, 256>>>(out);
}